// round 17
// baseline (speedup 1.0000x reference)
#include <cuda_runtime.h>
#include <cuda_bf16.h>
#include <stdint.h>

#define BATCH   8192
#define IN_DIM  2048
#define OUT_DIM 2048
#define DEPTH   5

// Tile bookkeeping: 1024 tiles of 128x128. First N_FULL run full-K; the last
// NSPLIT tiles are split into two half-K CTAs each (launched last).
#define N_TILES  1024
#define N_FULL   912
#define NSPLIT   (N_TILES - N_FULL)      // 112
#define GRID     (N_FULL + 2 * NSPLIT)   // 1136

// ---------------- device scratch (no allocs allowed) ----------------
__device__ __nv_bfloat16 g_A2[(size_t)2 * BATCH * IN_DIM];    // rows 0..8191 = hi(x), 8192.. = lo(x)
__device__ __nv_bfloat16 g_W2[(size_t)2 * OUT_DIM * IN_DIM];  // rows n = hi(W^T), 2048+n = lo(W^T)
__device__ float g_add[OUT_DIM];                              // bias + hd
__device__ float g_part[2][(size_t)NSPLIT * 128 * 128];       // split-K partials

// ---------------- PTX helpers (family-stable only) ----------------
__device__ __forceinline__ uint32_t smem_u32(const void* p) {
    uint32_t a;
    asm("{ .reg .u64 t; cvta.to.shared.u64 t, %1; cvt.u32.u64 %0, t; }" : "=r"(a) : "l"(p));
    return a;
}
__device__ __forceinline__ void cpa16(uint32_t s, const void* g) {
    asm volatile("cp.async.cg.shared.global [%0], [%1], 16;" :: "r"(s), "l"(g));
}
__device__ __forceinline__ void ldm4(uint32_t* r, uint32_t addr) {
    asm volatile("ldmatrix.sync.aligned.m8n8.x4.shared.b16 {%0,%1,%2,%3}, [%4];"
                 : "=r"(r[0]), "=r"(r[1]), "=r"(r[2]), "=r"(r[3]) : "r"(addr));
}
__device__ __forceinline__ void mma_bf16(float* c, const uint32_t* a, uint32_t b0, uint32_t b1) {
    asm volatile(
        "mma.sync.aligned.m16n8k16.row.col.f32.bf16.bf16.f32 "
        "{%0,%1,%2,%3}, {%4,%5,%6,%7}, {%8,%9}, {%0,%1,%2,%3};"
        : "+f"(c[0]), "+f"(c[1]), "+f"(c[2]), "+f"(c[3])
        : "r"(a[0]), "r"(a[1]), "r"(a[2]), "r"(a[3]), "r"(b0), "r"(b1));
}
__device__ __forceinline__ float tanh_apx(float x) {
    float y;
    asm("tanh.approx.f32 %0, %1;" : "=f"(y) : "f"(x));
    return y;
}
#define SWZ(o) ((o) ^ (((o) >> 3) & 0x70))

// ---------------- prepass kernels ----------------
__global__ void conv_a_kernel(const float* __restrict__ x) {
    size_t i = (size_t)blockIdx.x * blockDim.x + threadIdx.x;  // over 4.19M float4
    float4 v = ((const float4*)x)[i];
    __nv_bfloat16 h0 = __float2bfloat16(v.x), h1 = __float2bfloat16(v.y);
    __nv_bfloat16 h2 = __float2bfloat16(v.z), h3 = __float2bfloat16(v.w);
    __nv_bfloat16 l0 = __float2bfloat16(v.x - __bfloat162float(h0));
    __nv_bfloat16 l1 = __float2bfloat16(v.y - __bfloat162float(h1));
    __nv_bfloat16 l2 = __float2bfloat16(v.z - __bfloat162float(h2));
    __nv_bfloat16 l3 = __float2bfloat16(v.w - __bfloat162float(h3));
    __nv_bfloat162* Ah = (__nv_bfloat162*)g_A2;
    __nv_bfloat162* Al = (__nv_bfloat162*)(g_A2 + (size_t)BATCH * IN_DIM);
    __nv_bfloat162 p;
    p.x = h0; p.y = h1; Ah[i * 2 + 0] = p;
    p.x = h2; p.y = h3; Ah[i * 2 + 1] = p;
    p.x = l0; p.y = l1; Al[i * 2 + 0] = p;
    p.x = l2; p.y = l3; Al[i * 2 + 1] = p;
}

__global__ void conv_w_kernel(const float* __restrict__ W) {  // W:[IN_DIM][OUT_DIM] -> W^T hi/lo
    __shared__ float t[32][33];
    int bx = blockIdx.x * 32, by = blockIdx.y * 32;
    int tx = threadIdx.x, ty = threadIdx.y;
#pragma unroll
    for (int j = 0; j < 32; j += 8)
        t[ty + j][tx] = W[(size_t)(by + ty + j) * OUT_DIM + bx + tx];
    __syncthreads();
#pragma unroll
    for (int j = 0; j < 32; j += 8) {
        float v = t[tx][ty + j];                 // = W[by+tx][bx+ty+j]
        size_t n = bx + ty + j, k = by + tx;
        __nv_bfloat16 h = __float2bfloat16(v);
        __nv_bfloat16 l = __float2bfloat16(v - __bfloat162float(h));
        g_W2[n * IN_DIM + k] = h;
        g_W2[(OUT_DIM + n) * IN_DIM + k] = l;
    }
}

__global__ void hd_bias_kernel(const float* __restrict__ hdw, const float* __restrict__ bias) {
    int o = blockIdx.x * blockDim.x + threadIdx.x;
    if (o < OUT_DIM) {
        float p = 1.0f;
#pragma unroll
        for (int d = 0; d < DEPTH; ++d)
            p *= cosf(hdw[(size_t)d * IN_DIM * OUT_DIM + (size_t)o * OUT_DIM]);
        g_add[o] = bias[o] + p * p * (1.0f / (float)IN_DIM);
    }
}

// ---------------- mma.sync GEMM ----------------
// CTA tile M=128 x N=128, 4 warps (2m x 2n) of 64x64, fragment double-buffered,
// 3-stage cp.async pipeline, 2 CTAs/SM. K'=6144 -> 96 chunks (full) or 48 (split).
// Load path strength-reduced: per-thread swizzled smem offset and gmem pointer
// are precomputed; the 16-copy burst is cp.async with compile-time immediates.
#define A_BYTES  (128 * 128)                     // 16 KB
#define B_BYTES  (128 * 128)                     // 16 KB
#define STG_B    (A_BYTES + B_BYTES)             // 32 KB
#define NSTAGE   3
#define NT       128

// copies: 8 for A, 8 for B; row r = (tid>>3) + 16t, col byte = (tid&7)*16.
// smem: SWZ xor = (r&7)*16 is t-invariant -> off(t) = off0 + t*2048.
// gmem: ptr(t) = p0 + t*16*IN_DIM (constant byte stride 65536).
__device__ __forceinline__ void load_chunk2(const __nv_bfloat16* pa,
                                            const __nv_bfloat16* pb, uint32_t sA) {
#pragma unroll
    for (int t = 0; t < 8; ++t)
        cpa16(sA + t * 2048, pa + (size_t)t * (16 * IN_DIM));
#pragma unroll
    for (int t = 0; t < 8; ++t)
        cpa16(sA + A_BYTES + t * 2048, pb + (size_t)t * (16 * IN_DIM));
}

__global__ __launch_bounds__(NT, 2) void gemm_mma_kernel(float* __restrict__ C) {
    extern __shared__ char smem_raw[];
    const uint32_t s0 = smem_u32(smem_raw);
    const int tid = threadIdx.x;
    const int wid = tid >> 5, lane = tid & 31;
    const int warp_m = wid & 1, warp_n = wid >> 1;     // 2m x 2n of 64x64
    const int bid = blockIdx.x;

    // tile / K-range assignment
    int tile, c_lo, c_hi;
    float* part = (float*)0;
    if (bid < N_FULL) {
        tile = bid; c_lo = 0; c_hi = 96;
    } else {
        const int j = bid - N_FULL;
        tile = N_FULL + (j >> 1);
        const int h = j & 1;
        c_lo = h * 48; c_hi = c_lo + 48;
        part = g_part[h] + (size_t)(tile - N_FULL) * (128 * 128);
    }
    const int m0 = (tile >> 4) * 128;
    const int n0 = (tile & 15) * 128;

    // ---- precomputed load-path state (t-invariant parts) ----
    const int rb = tid >> 3, cb = tid & 7;
    const uint32_t soff = (uint32_t)(rb * 128) + (uint32_t)((cb * 16) ^ ((rb & 7) * 16));
    const __nv_bfloat16* pA0 = g_A2 + (size_t)(m0 + rb) * IN_DIM + cb * 8;
    const __nv_bfloat16* pB0 = g_W2 + (size_t)(n0 + rb) * IN_DIM + cb * 8;

#define CHUNK_PTRS(c_, pa_, pb_) \
    const __nv_bfloat16* pa_ = pA0 + (((c_) >= 64) ? (size_t)BATCH * IN_DIM : 0) + (((c_) & 31) << 6); \
    const __nv_bfloat16* pb_ = pB0 + ((((c_) >= 32) && ((c_) < 64)) ? (size_t)OUT_DIM * IN_DIM : 0) + (((c_) & 31) << 6)

    // XOR-folded ldmatrix addressing
    const int lrow = lane & 7;
    const int lt = lane >> 3;
    const uint32_t xo = (uint32_t)(lrow * 16);
    const int ra0 = warp_m * 64 + (lt & 1) * 8 + lrow;
    const int rb0 = warp_n * 64 + (lt & 1) * 8 + lrow;
    const uint32_t a_pre0 = (uint32_t)(ra0 * 128) | xo;
    const uint32_t b_pre0 = (uint32_t)(rb0 * 128) | xo;
    const uint32_t kbase = (lt >> 1) * 16;

    float acc[4][8][4];
#pragma unroll
    for (int i = 0; i < 4; ++i)
#pragma unroll
        for (int j = 0; j < 8; ++j)
#pragma unroll
            for (int q = 0; q < 4; ++q) acc[i][j][q] = 0.0f;

    uint32_t af[2][4][4], bf[2][4][4];

#define LD_FRAGS(B, Asb_, Bsb_, kof_) do {                          \
        const uint32_t _ax = (Asb_) + (a_pre0 ^ (uint32_t)(kof_));  \
        const uint32_t _bx = (Bsb_) + (b_pre0 ^ (uint32_t)(kof_));  \
        ldm4(af[B][0], _ax);                                        \
        ldm4(af[B][1], _ax + 2048);                                 \
        ldm4(af[B][2], _ax + 4096);                                 \
        ldm4(af[B][3], _ax + 6144);                                 \
        ldm4(bf[B][0], _bx);                                        \
        ldm4(bf[B][1], _bx + 2048);                                 \
        ldm4(bf[B][2], _bx + 4096);                                 \
        ldm4(bf[B][3], _bx + 6144);                                 \
    } while (0)

#define DO_MMA(B) do {                                                  \
        _Pragma("unroll")                                               \
        for (int mt = 0; mt < 4; ++mt)                                  \
            _Pragma("unroll")                                           \
            for (int np = 0; np < 4; ++np) {                            \
                mma_bf16(acc[mt][2 * np + 0], af[B][mt], bf[B][np][0], bf[B][np][2]); \
                mma_bf16(acc[mt][2 * np + 1], af[B][mt], bf[B][np][1], bf[B][np][3]); \
            }                                                           \
    } while (0)

    // prologue: fill 2 stages with chunks c_lo, c_lo+1; preload first frags
    {
        CHUNK_PTRS(c_lo, pa0, pb0);
        load_chunk2(pa0, pb0, s0 + soff);
        asm volatile("cp.async.commit_group;" ::: "memory");
        CHUNK_PTRS(c_lo + 1, pa1, pb1);
        load_chunk2(pa1, pb1, s0 + STG_B + soff);
        asm volatile("cp.async.commit_group;" ::: "memory");
    }
    asm volatile("cp.async.wait_group 1;" ::: "memory");
    __syncthreads();
    LD_FRAGS(0, s0, s0 + A_BYTES, kbase);

    uint32_t buf = 0, bnext = 1;
    for (int c = c_lo; c < c_hi; ++c) {
        asm volatile("cp.async.wait_group 0;" ::: "memory");
        __syncthreads();

        if (c + 2 < c_hi) {
            uint32_t b2 = bnext + 1; if (b2 == NSTAGE) b2 = 0;
            CHUNK_PTRS(c + 2, pa, pb);
            load_chunk2(pa, pb, s0 + b2 * STG_B + soff);
        }
        asm volatile("cp.async.commit_group;" ::: "memory");

        const uint32_t Asb = s0 + buf * STG_B;
        const uint32_t Bsb = Asb + A_BYTES;
#pragma unroll
        for (int ks = 0; ks < 4; ++ks) {
            const int fb = ks & 1;
            if (ks < 3) {
                LD_FRAGS(fb ^ 1, Asb, Bsb, (ks + 1) * 32 + kbase);
            } else if (c + 1 < c_hi) {
                const uint32_t sbn = s0 + bnext * STG_B;
                LD_FRAGS(fb ^ 1, sbn, sbn + A_BYTES, kbase);
            }
            DO_MMA(fb);
        }
        buf = bnext;
        if (++bnext == NSTAGE) bnext = 0;
    }

    // ---- epilogue ----
    const int g = lane >> 2, tig = lane & 3;
    if (part) {
        // split-K: store raw fp32 partials, tile-local 128x128 row-major
#pragma unroll
        for (int mt = 0; mt < 4; ++mt) {
            const int rl = warp_m * 64 + mt * 16 + g;
#pragma unroll
            for (int nt = 0; nt < 8; ++nt) {
                const int cl = warp_n * 64 + nt * 8 + tig * 2;
                float2 p0, p1;
                p0.x = acc[mt][nt][0]; p0.y = acc[mt][nt][1];
                p1.x = acc[mt][nt][2]; p1.y = acc[mt][nt][3];
                *(float2*)(part + rl * 128 + cl) = p0;
                *(float2*)(part + (rl + 8) * 128 + cl) = p1;
            }
        }
    } else {
#pragma unroll
        for (int mt = 0; mt < 4; ++mt) {
            const int r0 = m0 + warp_m * 64 + mt * 16 + g;
#pragma unroll
            for (int nt = 0; nt < 8; ++nt) {
                const int col = n0 + warp_n * 64 + nt * 8 + tig * 2;
                const float a0 = __ldg(&g_add[col]);
                const float a1 = __ldg(&g_add[col + 1]);
                float2 o0, o1;
                o0.x = tanh_apx(acc[mt][nt][0] + a0);
                o0.y = tanh_apx(acc[mt][nt][1] + a1);
                o1.x = tanh_apx(acc[mt][nt][2] + a0);
                o1.y = tanh_apx(acc[mt][nt][3] + a1);
                *(float2*)(C + (size_t)r0 * OUT_DIM + col) = o0;
                *(float2*)(C + (size_t)(r0 + 8) * OUT_DIM + col) = o1;
            }
        }
    }
}

// ---------------- merge kernel for split tiles ----------------
__global__ void merge_kernel(float* __restrict__ C) {
    const size_t i = (size_t)blockIdx.x * blockDim.x + threadIdx.x;  // over NSPLIT*16384/4
    float4 p0 = ((const float4*)g_part[0])[i];
    float4 p1 = ((const float4*)g_part[1])[i];
    const size_t e = i * 4;
    const int tile = N_FULL + (int)(e >> 14);
    const int within = (int)(e & 16383);
    const int row = within >> 7, col = within & 127;
    const int m = (tile >> 4) * 128 + row;
    const int n = (tile & 15) * 128 + col;
    float4 o;
    o.x = tanh_apx(p0.x + p1.x + g_add[n + 0]);
    o.y = tanh_apx(p0.y + p1.y + g_add[n + 1]);
    o.z = tanh_apx(p0.z + p1.z + g_add[n + 2]);
    o.w = tanh_apx(p0.w + p1.w + g_add[n + 3]);
    *(float4*)(C + (size_t)m * OUT_DIM + n) = o;
}

// ---------------- launch ----------------
#define GEMM_SMEM (NSTAGE * STG_B)   // 96 KB per CTA, 2 CTAs/SM

extern "C" void kernel_launch(void* const* d_in, const int* in_sizes, int n_in,
                              void* d_out, int out_size) {
    const float* x   = (const float*)d_in[0];  // [8192, 2048]
    const float* hdw = (const float*)d_in[1];  // [5, 2048, 2048]
    const float* W   = (const float*)d_in[2];  // [2048, 2048]
    const float* b   = (const float*)d_in[3];  // [2048]
    float* out = (float*)d_out;                // [8192, 2048]

    cudaFuncSetAttribute(gemm_mma_kernel, cudaFuncAttributeMaxDynamicSharedMemorySize, GEMM_SMEM);

    conv_a_kernel<<<(BATCH * IN_DIM / 4) / 256, 256>>>(x);
    conv_w_kernel<<<dim3(OUT_DIM / 32, IN_DIM / 32), dim3(32, 8)>>>(W);
    hd_bias_kernel<<<OUT_DIM / 256, 256>>>(hdw, b);

    gemm_mma_kernel<<<GRID, NT, GEMM_SMEM>>>(out);
    merge_kernel<<<(NSPLIT * 128 * 128 / 4) / 256, 256>>>(out);
}